// round 1
// baseline (speedup 1.0000x reference)
#include <cuda_runtime.h>
#include <cstdint>

// Problem constants
#define B_    64
#define P_    56
#define N_    3136      // P*P
#define DIM_  256
#define HEADS_ 4
#define HD_   24
#define M_    16
#define OUT_  256
#define BH_   256       // B*HEADS
#define CJ_   192       // HEADS*HD*2 (feat+val fused columns)

// ---------------- scratch (no allocation allowed; __device__ globals) ----------------
__device__ float g_f[(size_t)BH_ * N_ * HD_];            // [bh][n][hd]  77 MB
__device__ float g_v[(size_t)BH_ * N_ * HD_];            // [bh][n][hd]  77 MB
__device__ float g_centers_n[BH_ * M_ * HD_];            // normalized centers
__device__ float g_value_centers[BH_ * M_ * HD_];
__device__ float g_agg[BH_ * M_ * HD_];
__device__ int   g_assign[(size_t)BH_ * N_];
__device__ float g_sval[(size_t)BH_ * N_];

// =====================================================================
// K1: fused feat/val GEMM.  out[r, 0..191] = x[r,:] @ [f_w; v_w]^T + bias
// Epilogue scatters into head-split layout g_f / g_v.
// Tile: 64 rows x 192 cols, 256 threads, 8x6 per thread, K-chunk 32.
// =====================================================================
__global__ __launch_bounds__(256) void k_gemm_fv(
    const float* __restrict__ x,
    const float* __restrict__ f_w, const float* __restrict__ f_b,
    const float* __restrict__ v_w, const float* __restrict__ v_b)
{
    __shared__ float Xs[64][33];
    __shared__ float Ws[192][33];

    const int tid = threadIdx.x;
    const int tx = tid & 31;          // 0..31 -> column lane
    const int ty = tid >> 5;          // 0..7  -> row lane
    const int r0 = blockIdx.x * 64;   // 3136 % 64 == 0 -> uniform batch b
    const int bb = r0 / N_;

    float acc[8][6];
#pragma unroll
    for (int i = 0; i < 8; i++)
#pragma unroll
        for (int j = 0; j < 6; j++) acc[i][j] = 0.f;

    for (int kc = 0; kc < DIM_; kc += 32) {
        // load X tile: 64x32 = 512 float4
#pragma unroll
        for (int l = tid; l < 512; l += 256) {
            int row = l >> 3, q = l & 7;
            float4 t = *(const float4*)(x + (size_t)(r0 + row) * DIM_ + kc + q * 4);
            Xs[row][q * 4 + 0] = t.x; Xs[row][q * 4 + 1] = t.y;
            Xs[row][q * 4 + 2] = t.z; Xs[row][q * 4 + 3] = t.w;
        }
        // load W tile: 192x32 = 1536 float4 (rows 0..95 from f_w, 96..191 from v_w)
#pragma unroll
        for (int l = tid; l < 1536; l += 256) {
            int row = l >> 3, q = l & 7;
            const float* src = (row < 96) ? (f_w + (size_t)row * DIM_)
                                          : (v_w + (size_t)(row - 96) * DIM_);
            float4 t = *(const float4*)(src + kc + q * 4);
            Ws[row][q * 4 + 0] = t.x; Ws[row][q * 4 + 1] = t.y;
            Ws[row][q * 4 + 2] = t.z; Ws[row][q * 4 + 3] = t.w;
        }
        __syncthreads();
#pragma unroll
        for (int kk = 0; kk < 32; kk++) {
            float a[8], w[6];
#pragma unroll
            for (int i = 0; i < 8; i++) a[i] = Xs[i * 8 + ty][kk];   // warp broadcast
#pragma unroll
            for (int j = 0; j < 6; j++) w[j] = Ws[j * 32 + tx][kk];  // conflict-free
#pragma unroll
            for (int i = 0; i < 8; i++)
#pragma unroll
                for (int j = 0; j < 6; j++)
                    acc[i][j] = fmaf(a[i], w[j], acc[i][j]);
        }
        __syncthreads();
    }

    // scatter into head-split layout
#pragma unroll
    for (int i = 0; i < 8; i++) {
        int r = r0 + i * 8 + ty;
        int n = r - bb * N_;
#pragma unroll
        for (int j = 0; j < 6; j++) {
            int col = j * 32 + tx;
            if (col < 96) {
                int e = col / HD_, c = col % HD_;
                g_f[((size_t)(bb * HEADS_ + e) * N_ + n) * HD_ + c] = acc[i][j] + f_b[col];
            } else {
                int col2 = col - 96;
                int e = col2 / HD_, c = col2 % HD_;
                g_v[((size_t)(bb * HEADS_ + e) * N_ + n) * HD_ + c] = acc[i][j] + v_b[col2];
            }
        }
    }
}

// =====================================================================
// K2: adaptive-avg-pool to (4,4) + L2-normalize centers.
// 1 block per (bh, m); 192 threads = 8 partials x 24 channels.
// =====================================================================
__global__ __launch_bounds__(192) void k_pool()
{
    __shared__ float sf[192], sv[192];
    __shared__ float cf[24];
    __shared__ float norm_inv;

    const int g  = blockIdx.x;
    const int bh = g >> 4;
    const int m  = g & 15;
    const int pw = m >> 2, ph = m & 3;
    const int tid = threadIdx.x;
    const int c = tid % 24, part = tid / 24;

    float af = 0.f, av = 0.f;
    for (int it = part; it < 196; it += 8) {
        int dw = it / 14, dh = it % 14;
        int n = (pw * 14 + dw) * P_ + ph * 14 + dh;
        size_t idx = ((size_t)bh * N_ + n) * HD_ + c;
        af += g_f[idx];
        av += g_v[idx];
    }
    sf[tid] = af; sv[tid] = av;
    __syncthreads();

    if (tid < 24) {
        float s1 = 0.f, s2 = 0.f;
#pragma unroll
        for (int p = 0; p < 8; p++) { s1 += sf[p * 24 + tid]; s2 += sv[p * 24 + tid]; }
        float mf = s1 * (1.f / 196.f);
        float mv = s2 * (1.f / 196.f);
        g_value_centers[(bh * M_ + m) * HD_ + tid] = mv;
        cf[tid] = mf;
    }
    __syncthreads();
    if (tid == 0) {
        float ss = 0.f;
#pragma unroll
        for (int k = 0; k < 24; k++) ss += cf[k] * cf[k];
        norm_inv = 1.f / fmaxf(sqrtf(ss), 1e-12f);
    }
    __syncthreads();
    if (tid < 24)
        g_centers_n[(bh * M_ + m) * HD_ + tid] = cf[tid] * norm_inv;
}

// =====================================================================
// K3: per-bh clustering. 1 block per bh (256 blocks, 512 threads).
// Phase 1: per-token similarity vs 16 normalized centers -> leaky-relu
//          transform -> argmax (first-index tie-break) -> assign + s.
// Phase 2: warp w (=center w) scans tokens from shared; accumulates
//          s * v without any atomics; finalizes agg = (sum+vc)/(cnt+1).
// =====================================================================
__global__ __launch_bounds__(512) void k_cluster(
    const float* __restrict__ sim_alpha, const float* __restrict__ sim_beta)
{
    __shared__ float cn[M_ * HD_];          // normalized centers
    __shared__ unsigned char assign_sh[N_];
    __shared__ float sval_sh[N_];

    const int bh  = blockIdx.x;
    const int tid = threadIdx.x;
    const float alpha = sim_alpha[0];
    const float beta  = sim_beta[0];

    for (int l = tid; l < M_ * HD_; l += 512)
        cn[l] = g_centers_n[bh * M_ * HD_ + l];
    __syncthreads();

    // ---- phase 1 ----
    for (int n = tid; n < N_; n += 512) {
        float fv[24];
        const float4* fp4 = (const float4*)(g_f + ((size_t)bh * N_ + n) * HD_);
#pragma unroll
        for (int q = 0; q < 6; q++) {
            float4 t = fp4[q];
            fv[q * 4 + 0] = t.x; fv[q * 4 + 1] = t.y;
            fv[q * 4 + 2] = t.z; fv[q * 4 + 3] = t.w;
        }
        float ss = 0.f;
#pragma unroll
        for (int k = 0; k < 24; k++) ss += fv[k] * fv[k];
        float inv = 1.f / fmaxf(sqrtf(ss), 1e-12f);

        float best = -3.402823466e38f;
        int bi = 0;
#pragma unroll
        for (int m = 0; m < M_; m++) {
            float d = 0.f;
#pragma unroll
            for (int k = 0; k < 24; k++) d = fmaf(cn[m * HD_ + k], fv[k], d);
            float t = beta + alpha * (d * inv);
            t = (t >= 0.f) ? t : 0.2f * t;          // leaky_relu 0.2
            if (t > best) { best = t; bi = m; }     // first index wins ties
        }
        assign_sh[n] = (unsigned char)bi;
        sval_sh[n]   = best;
        g_assign[(size_t)bh * N_ + n] = bi;
        g_sval[(size_t)bh * N_ + n]   = best;
    }
    __syncthreads();

    // ---- phase 2: warp per center ----
    const int w    = tid >> 5;   // center 0..15
    const int lane = tid & 31;

    float acc[24];
#pragma unroll
    for (int k = 0; k < 24; k++) acc[k] = 0.f;
    int cnt = 0;

    for (int n = lane; n < N_; n += 32) {
        if (assign_sh[n] == (unsigned char)w) {
            float s = sval_sh[n];
            const float4* vp4 = (const float4*)(g_v + ((size_t)bh * N_ + n) * HD_);
#pragma unroll
            for (int q = 0; q < 6; q++) {
                float4 t = vp4[q];
                acc[q * 4 + 0] = fmaf(s, t.x, acc[q * 4 + 0]);
                acc[q * 4 + 1] = fmaf(s, t.y, acc[q * 4 + 1]);
                acc[q * 4 + 2] = fmaf(s, t.z, acc[q * 4 + 2]);
                acc[q * 4 + 3] = fmaf(s, t.w, acc[q * 4 + 3]);
            }
            cnt++;
        }
    }
#pragma unroll
    for (int off = 16; off > 0; off >>= 1) {
#pragma unroll
        for (int k = 0; k < 24; k++)
            acc[k] += __shfl_xor_sync(0xffffffffu, acc[k], off);
        cnt += __shfl_xor_sync(0xffffffffu, cnt, off);
    }
    if (lane == 0) {
        float denom = 1.f / ((float)cnt + 1.f);
        const float* vc = g_value_centers + (bh * M_ + w) * HD_;
        float* dst = g_agg + (bh * M_ + w) * HD_;
#pragma unroll
        for (int k = 0; k < 24; k++)
            dst[k] = (acc[k] + vc[k]) * denom;
    }
}

// =====================================================================
// K5: dispatch + output projection, fused.
// merged[n, e*24+k] = s_{bh,n} * agg[bh, c_{bh,n}, k];  out = merged @ proj_w^T + b
// Block: 64 tokens x 256 out channels; 256 threads; 8x8 per thread; K-chunk 16.
// =====================================================================
__global__ __launch_bounds__(256) void k_out(
    const float* __restrict__ proj_w, const float* __restrict__ proj_b,
    float* __restrict__ out)
{
    __shared__ float agg_sh[HEADS_ * M_ * HD_];   // 1536 floats
    __shared__ float Ms[64][97];                  // merged vectors (96 + pad)
    __shared__ float Wp[256][17];                 // proj chunk (16 + pad)

    const int bb = blockIdx.y;
    const int n0 = blockIdx.x * 64;
    const int tid = threadIdx.x;
    const int tx = tid & 31;   // channel lane
    const int ty = tid >> 5;   // token lane

    for (int l = tid; l < 1536; l += 256)
        agg_sh[l] = g_agg[(size_t)bb * 1536 + l];
    __syncthreads();

    {   // build merged vectors: thread -> (token, head)
        int tok = tid >> 2, e = tid & 3;
        int n = n0 + tok;
        size_t ix = (size_t)(bb * HEADS_ + e) * N_ + n;
        int   c = g_assign[ix];
        float s = g_sval[ix];
#pragma unroll
        for (int k = 0; k < 24; k++)
            Ms[tok][e * HD_ + k] = s * agg_sh[(e * M_ + c) * HD_ + k];
    }

    float acc[8][8];
#pragma unroll
    for (int i = 0; i < 8; i++)
#pragma unroll
        for (int j = 0; j < 8; j++) acc[i][j] = 0.f;

    for (int kc = 0; kc < 96; kc += 16) {
        __syncthreads();   // Ms ready (iter 0) / previous Wp consumed (iter>0)
        // load Wp: 256x16 = 1024 float4
        for (int l = tid; l < 1024; l += 256) {
            int row = l >> 2, q = l & 3;
            float4 t = *(const float4*)(proj_w + (size_t)row * 96 + kc + q * 4);
            Wp[row][q * 4 + 0] = t.x; Wp[row][q * 4 + 1] = t.y;
            Wp[row][q * 4 + 2] = t.z; Wp[row][q * 4 + 3] = t.w;
        }
        __syncthreads();
#pragma unroll
        for (int kk = 0; kk < 16; kk++) {
            float a[8], w[8];
#pragma unroll
            for (int i = 0; i < 8; i++) a[i] = Ms[i * 8 + ty][kc + kk];   // broadcast
#pragma unroll
            for (int j = 0; j < 8; j++) w[j] = Wp[j * 32 + tx][kk];       // conflict-free
#pragma unroll
            for (int i = 0; i < 8; i++)
#pragma unroll
                for (int j = 0; j < 8; j++)
                    acc[i][j] = fmaf(a[i], w[j], acc[i][j]);
        }
    }

#pragma unroll
    for (int i = 0; i < 8; i++) {
        int n = n0 + i * 8 + ty;
#pragma unroll
        for (int j = 0; j < 8; j++) {
            int ch = j * 32 + tx;
            out[((size_t)(bb * N_ + n)) * OUT_ + ch] = acc[i][j] + proj_b[ch];
        }
    }
}

// =====================================================================
extern "C" void kernel_launch(void* const* d_in, const int* in_sizes, int n_in,
                              void* d_out, int out_size)
{
    (void)in_sizes; (void)n_in; (void)out_size;
    const float* x         = (const float*)d_in[0];
    const float* f_w       = (const float*)d_in[1];
    const float* f_b       = (const float*)d_in[2];
    const float* v_w       = (const float*)d_in[3];
    const float* v_b       = (const float*)d_in[4];
    const float* proj_w    = (const float*)d_in[5];
    const float* proj_b    = (const float*)d_in[6];
    const float* sim_alpha = (const float*)d_in[7];
    const float* sim_beta  = (const float*)d_in[8];
    float* out = (float*)d_out;

    k_gemm_fv<<<(B_ * N_) / 64, 256>>>(x, f_w, f_b, v_w, v_b);
    k_pool<<<BH_ * M_, 192>>>();
    k_cluster<<<BH_, 512>>>(sim_alpha, sim_beta);
    dim3 g5(N_ / 64, B_);
    k_out<<<g5, 256>>>(proj_w, proj_b, out);
}